// round 12
// baseline (speedup 1.0000x reference)
#include <cuda_runtime.h>
#include <cuda_bf16.h>
#include <cstdint>

// ---------------- problem constants -----------------------------------------
static constexpr int BB = 16, CIN = 64, H = 32, W = 32, COUT = 64;
static constexpr int GS = 8;
static constexpr int HP = 34, WP = 34;
static constexpr int CK = CIN * GS;           // 512 effective channels

// ---------------- device scratch (no allocations allowed) -------------------
// basis planes, channel-last, tf32-rounded fp32, k-permuted within each 8-block
__device__ __align__(16) float g_yf[BB * HP * WP * CK];   // ~37.9 MB
// folded weights, tf32-rounded fp32, same k permutation: [tap][o][c']
__device__ __align__(16) float g_wt[9 * COUT * CK];
// partial sums for K-split half 1
__device__ __align__(16) float g_part[BB * COUT * H * W]; // 4 MB

// ---------------- helpers -----------------------------------------------------
__device__ __forceinline__ uint32_t smem_u32(const void* p) {
    uint32_t a;
    asm("{ .reg .u64 t; cvta.to.shared.u64 t, %1; cvt.u32.u64 %0, t; }"
        : "=r"(a) : "l"(p));
    return a;
}
__device__ __forceinline__ void cp16(uint32_t dst, const void* src) {
    asm volatile("cp.async.ca.shared.global [%0], [%1], 16;"
                 :: "r"(dst), "l"(src) : "memory");
}
__device__ __forceinline__ void lds64(uint32_t addr, uint32_t& r0, uint32_t& r1) {
    asm volatile("ld.shared.v2.b32 {%0,%1}, [%2];"
                 : "=r"(r0), "=r"(r1) : "r"(addr));
}
__device__ __forceinline__ void mma1688(float* c, uint32_t a0, uint32_t a1,
                                        uint32_t a2, uint32_t a3,
                                        uint32_t b0, uint32_t b1) {
    asm volatile(
        "mma.sync.aligned.m16n8k8.row.col.f32.tf32.tf32.f32 "
        "{%0,%1,%2,%3}, {%4,%5,%6,%7}, {%8,%9}, {%0,%1,%2,%3};"
        : "+f"(c[0]), "+f"(c[1]), "+f"(c[2]), "+f"(c[3])
        : "r"(a0), "r"(a1), "r"(a2), "r"(a3), "r"(b0), "r"(b1));
}
__device__ __forceinline__ float tf32r(float v) {
    uint32_t u;
    asm("cvt.rna.tf32.f32 %0, %1;" : "=r"(u) : "f"(v));
    return __uint_as_float(u);
}

// ---------------- kernel 1: weight fold + tf32 round + k-permute ------------
__global__ void wprep_kernel(const float* __restrict__ sw,
                             const float* __restrict__ sc) {
    int t = blockIdx.x * blockDim.x + threadIdx.x;
    if (t >= 9 * COUT * CK) return;
    int c = t & 511;
    int o = (t >> 9) & 63;
    int tap = t >> 15;
    int i = c >> 3, g = c & 7;
    float v = sw[((o * CIN + i) * GS + g) * 9 + tap] * sc[o * CIN + i];
    int slot = ((g << 1) & 7) | (g >> 2);
    g_wt[(t & ~7) | slot] = tf32r(v);
}

// ---------------- kernel 2: B-spline basis, tf32 fp32, k-permuted ------------
__global__ void basis_kernel(const float* __restrict__ x) {
    int idx = blockIdx.x * blockDim.x + threadIdx.x;
    if (idx >= BB * HP * WP * CIN) return;
    int i = idx & 63;
    int t = idx >> 6;
    int wp = t % WP; t /= WP;
    int hp = t % HP;
    int b = t / HP;

    float xv = 0.0f;
    int h = hp - 1, w = wp - 1;
    if ((unsigned)h < (unsigned)H && (unsigned)w < (unsigned)W)
        xv = x[((b * CIN + i) * H + h) * W + w];

    float gk[12];
#pragma unroll
    for (int j = 0; j < 12; j++) gk[j] = (float)(j - 3) * 0.4f - 1.0f;
    float b0[11];
#pragma unroll
    for (int j = 0; j < 11; j++)
        b0[j] = (xv >= gk[j] && xv < gk[j + 1]) ? 1.0f : 0.0f;
    float b1[10];
#pragma unroll
    for (int j = 0; j < 10; j++)
        b1[j] = ((xv - gk[j]) * b0[j] + (gk[j + 2] - xv) * b0[j + 1]) * 2.5f;
    float b2[9];
#pragma unroll
    for (int j = 0; j < 9; j++)
        b2[j] = ((xv - gk[j]) * b1[j] + (gk[j + 3] - xv) * b1[j + 1]) * 1.25f;
    float b3[8];
#pragma unroll
    for (int j = 0; j < 8; j++)
        b3[j] = ((xv - gk[j]) * b2[j] + (gk[j + 4] - xv) * b2[j + 1]) * (1.0f / 1.2f);

    float f[8];
#pragma unroll
    for (int g = 0; g < GS; g++) {
        int slot = ((g << 1) & 7) | (g >> 2);
        f[slot] = tf32r(b3[g]);
    }
    float4* dst = (float4*)(g_yf + (size_t)idx * 8);
    dst[0] = make_float4(f[0], f[1], f[2], f[3]);
    dst[1] = make_float4(f[4], f[5], f[6], f[7]);
}

// ---------------- kernel 3: tf32 mma.sync conv, K-split across 2 CTAs --------
// CTA: M=64 pixels (batch b, 2 rows x 32 cols), N=64 outs, 128 thr / 4 warps,
// processes 4 of 8 channel chunks (kh = blockIdx.y). kh0 -> out, kh1 -> g_part.
static constexpr int A_BYTES = 136 * 256;        // 34816
static constexpr int B_BYTES = 16384;
static constexpr int SMEM_TOTAL = A_BYTES + 2 * B_BYTES + 256;

__global__ __launch_bounds__(128, 3) void conv_kernel(float* __restrict__ out) {
    extern __shared__ char smem[];
    uint32_t sraw = smem_u32(smem);
    uint32_t sb = (sraw + 255u) & ~255u;
    uint32_t Ab = sb;
    uint32_t Bb0 = sb + A_BYTES;

    int tid = threadIdx.x;
    int blk = blockIdx.x;
    int kh = blockIdx.y;          // K half: chunks [kh*4, kh*4+4)
    int bb = blk >> 4;
    int h0 = (blk & 15) * 2;

    int lane = tid & 31;
    int wrp = tid >> 5;
    int wm = wrp & 1, wn = wrp >> 1;
    int n0w = wn * 32;
    int g = lane >> 2, t4 = lane & 3;

    uint32_t boff[4];
#pragma unroll
    for (int nf = 0; nf < 4; nf++)
        boff[nf] = (uint32_t)((n0w + nf * 8 + g) * 256 + t4 * 8 + (g << 5));

    float acc[2][4][4];
#pragma unroll
    for (int a = 0; a < 2; a++)
#pragma unroll
        for (int b = 0; b < 4; b++)
#pragma unroll
            for (int i = 0; i < 4; i++) acc[a][b][i] = 0.0f;

    const uint4* yf4 = (const uint4*)g_yf;
    const uint4* wt4 = (const uint4*)g_wt;

    auto issueA = [&](int ch) {
        int cw0 = ch * 16;
#pragma unroll
        for (int k = 0; k < 17; k++) {
            int q = tid + k * 128;
            int pix = q >> 4, c4 = q & 15;
            int r = pix / 34, wp = pix - r * 34;
            uint32_t dst = Ab + pix * 256 + ((c4 ^ ((pix & 7) << 1)) << 4);
            cp16(dst, yf4 + (((bb * HP + h0 + r) * WP + wp) * 128 + cw0 + c4));
        }
    };
    auto issueB = [&](int tap, int ch, int buf) {
        int cw0 = ch * 16;
        uint32_t base = Bb0 + buf * B_BYTES;
#pragma unroll
        for (int k = 0; k < 8; k++) {
            int q = tid + k * 128;
            int o = q >> 4, c4 = q & 15;
            uint32_t dst = base + o * 256 + ((c4 ^ ((o & 7) << 1)) << 4);
            cp16(dst, wt4 + ((tap * COUT + o) * 128 + cw0 + c4));
        }
    };

    auto compute = [&](int tap, int buf) {
        int tk = tap / 3, tl = tap - 3 * tk;
        int prow = wm + tk;
        uint32_t apx[2][2];
#pragma unroll
        for (int mt = 0; mt < 2; mt++)
#pragma unroll
            for (int hf = 0; hf < 2; hf++) {
                int p = prow * 34 + mt * 16 + g + hf * 8 + tl;
                apx[mt][hf] = (uint32_t)(p * 256 + t4 * 8 + ((p & 7) << 5));
            }
        uint32_t bbase = Bb0 + buf * B_BYTES;
#pragma unroll
        for (int ks = 0; ks < 8; ks++) {
            uint32_t xo = (uint32_t)(ks << 5);
            uint32_t a0[2], a1[2], a2[2], a3[2];
#pragma unroll
            for (int mt = 0; mt < 2; mt++) {
                lds64(Ab + (apx[mt][0] ^ xo), a0[mt], a2[mt]);
                lds64(Ab + (apx[mt][1] ^ xo), a1[mt], a3[mt]);
            }
            uint32_t b0[4], b1[4];
#pragma unroll
            for (int nf = 0; nf < 4; nf++)
                lds64(bbase + (boff[nf] ^ xo), b0[nf], b1[nf]);
#pragma unroll
            for (int mt = 0; mt < 2; mt++)
#pragma unroll
                for (int nf = 0; nf < 4; nf++)
                    mma1688(acc[mt][nf], a0[mt], a1[mt], a2[mt], a3[mt],
                            b0[nf], b1[nf]);
        }
    };

    // ---- pipeline over 4 chunks x 9 taps ------------------------------------
    int ch0 = kh * 4;
    issueA(ch0);
    issueB(0, ch0, 0);
    asm volatile("cp.async.commit_group;" ::: "memory");
    asm volatile("cp.async.wait_group 0;" ::: "memory");
    __syncthreads();

    int cur = 0;
    for (int cc = 0; cc < 4; cc++) {
        int ch = ch0 + cc;
        for (int tap = 0; tap < 9; tap++) {
            bool hn = (tap < 8);
            if (hn) {
                issueB(tap + 1, ch, cur ^ 1);
                asm volatile("cp.async.commit_group;" ::: "memory");
            }
            compute(tap, cur);
            if (hn) asm volatile("cp.async.wait_group 0;" ::: "memory");
            __syncthreads();
            if (hn) cur ^= 1;
        }
        if (cc < 3) {
            issueA(ch + 1);
            issueB(0, ch + 1, cur ^ 1);
            asm volatile("cp.async.commit_group;" ::: "memory");
            asm volatile("cp.async.wait_group 0;" ::: "memory");
            __syncthreads();
            cur ^= 1;
        }
    }

    // ---- epilogue -----------------------------------------------------------
    float* dst = (kh == 0) ? out : g_part;
    int hrow = h0 + wm;
    float* obase = dst + ((size_t)bb * COUT) * (H * W) + hrow * W;
#pragma unroll
    for (int mt = 0; mt < 2; mt++) {
        int wcol = mt * 16 + g;
#pragma unroll
        for (int nf = 0; nf < 4; nf++) {
            int o = n0w + nf * 8 + 2 * t4;
            obase[o * (H * W) + wcol]           = acc[mt][nf][0];
            obase[(o + 1) * (H * W) + wcol]     = acc[mt][nf][1];
            obase[o * (H * W) + wcol + 8]       = acc[mt][nf][2];
            obase[(o + 1) * (H * W) + wcol + 8] = acc[mt][nf][3];
        }
    }
}

// ---------------- kernel 4: merge K-split halves ------------------------------
__global__ void reduce_kernel(float* __restrict__ out) {
    int i = blockIdx.x * blockDim.x + threadIdx.x;
    int n4 = (BB * COUT * H * W) / 4;
    if (i >= n4) return;
    float4 a = ((const float4*)out)[i];
    float4 b = ((const float4*)g_part)[i];
    ((float4*)out)[i] = make_float4(a.x + b.x, a.y + b.y, a.z + b.z, a.w + b.w);
}

// ---------------- launch ------------------------------------------------------
extern "C" void kernel_launch(void* const* d_in, const int* in_sizes, int n_in,
                              void* d_out, int out_size) {
    const float* x  = (const float*)d_in[0];   // [16,64,32,32]
    const float* sw = (const float*)d_in[1];   // [64,64,8,3,3]
    const float* sc = (const float*)d_in[2];   // [64,64]
    float* out = (float*)d_out;                // [16,64,32,32]

    cudaFuncSetAttribute(conv_kernel,
                         cudaFuncAttributeMaxDynamicSharedMemorySize,
                         SMEM_TOTAL);

    {
        int n = 9 * COUT * CK;
        wprep_kernel<<<(n + 255) / 256, 256>>>(sw, sc);
    }
    {
        int n = BB * HP * WP * CIN;
        basis_kernel<<<(n + 255) / 256, 256>>>(x);
    }
    {
        dim3 grid(BB * (H / 2), 2);
        conv_kernel<<<grid, 128, SMEM_TOTAL>>>(out);
    }
    {
        int n4 = (BB * COUT * H * W) / 4;
        reduce_kernel<<<(n4 + 255) / 256, 256>>>(out);
    }
}

// round 15
// speedup vs baseline: 1.8500x; 1.8500x over previous
#include <cuda_runtime.h>
#include <cuda_fp16.h>
#include <cstdint>

// ---------------- problem constants -----------------------------------------
static constexpr int BB = 16, CIN = 64, H = 32, W = 32, COUT = 64;
static constexpr int GS = 8;
static constexpr int HP = 34, WP = 34;
static constexpr int CK = CIN * GS;           // 512 effective channels

// ---------------- device scratch (no allocations allowed) -------------------
// basis planes, channel-last fp16: [b][hp][wp][c=i*8+g]
__device__ __align__(16) __half g_yh[BB * HP * WP * CK];   // ~18.9 MB
// folded weights fp16: [tap][o][c]
__device__ __align__(16) __half g_wh[9 * COUT * CK];

// ---------------- helpers -----------------------------------------------------
__device__ __forceinline__ uint32_t smem_u32(const void* p) {
    uint32_t a;
    asm("{ .reg .u64 t; cvta.to.shared.u64 t, %1; cvt.u32.u64 %0, t; }"
        : "=r"(a) : "l"(p));
    return a;
}
__device__ __forceinline__ void cp16(uint32_t dst, const void* src) {
    asm volatile("cp.async.ca.shared.global [%0], [%1], 16;"
                 :: "r"(dst), "l"(src) : "memory");
}
__device__ __forceinline__ void ldm4(uint32_t addr, uint32_t& r0, uint32_t& r1,
                                     uint32_t& r2, uint32_t& r3) {
    asm volatile("ldmatrix.sync.aligned.m8n8.x4.shared.b16 {%0,%1,%2,%3}, [%4];"
                 : "=r"(r0), "=r"(r1), "=r"(r2), "=r"(r3) : "r"(addr));
}
__device__ __forceinline__ void mma16816(float* c, const uint32_t* a,
                                         uint32_t b0, uint32_t b1) {
    asm volatile(
        "mma.sync.aligned.m16n8k16.row.col.f32.f16.f16.f32 "
        "{%0,%1,%2,%3}, {%4,%5,%6,%7}, {%8,%9}, {%0,%1,%2,%3};"
        : "+f"(c[0]), "+f"(c[1]), "+f"(c[2]), "+f"(c[3])
        : "r"(a[0]), "r"(a[1]), "r"(a[2]), "r"(a[3]), "r"(b0), "r"(b1));
}

// ---------------- kernel 1: weight fold -> fp16 [tap][o][c] -------------------
__global__ void wprep_kernel(const float* __restrict__ sw,
                             const float* __restrict__ sc) {
    int t = blockIdx.x * blockDim.x + threadIdx.x;
    if (t >= 9 * COUT * CK) return;
    int c = t & 511;
    int o = (t >> 9) & 63;
    int tap = t >> 15;
    int i = c >> 3, g = c & 7;
    float v = sw[((o * CIN + i) * GS + g) * 9 + tap] * sc[o * CIN + i];
    g_wh[(tap * COUT + o) * CK + c] = __float2half(v);
}

// ---------------- kernel 2: B-spline basis -> fp16 [b][hp][wp][c] -------------
__global__ void basis_kernel(const float* __restrict__ x) {
    int idx = blockIdx.x * blockDim.x + threadIdx.x;
    if (idx >= BB * HP * WP * CIN) return;
    int i = idx & 63;
    int t = idx >> 6;
    int wp = t % WP; t /= WP;
    int hp = t % HP;
    int b = t / HP;

    float xv = 0.0f;
    int h = hp - 1, w = wp - 1;
    if ((unsigned)h < (unsigned)H && (unsigned)w < (unsigned)W)
        xv = x[((b * CIN + i) * H + h) * W + w];

    float gk[12];
#pragma unroll
    for (int j = 0; j < 12; j++) gk[j] = (float)(j - 3) * 0.4f - 1.0f;
    float b0[11];
#pragma unroll
    for (int j = 0; j < 11; j++)
        b0[j] = (xv >= gk[j] && xv < gk[j + 1]) ? 1.0f : 0.0f;
    float b1[10];
#pragma unroll
    for (int j = 0; j < 10; j++)
        b1[j] = ((xv - gk[j]) * b0[j] + (gk[j + 2] - xv) * b0[j + 1]) * 2.5f;
    float b2[9];
#pragma unroll
    for (int j = 0; j < 9; j++)
        b2[j] = ((xv - gk[j]) * b1[j] + (gk[j + 3] - xv) * b1[j + 1]) * 1.25f;
    float b3[8];
#pragma unroll
    for (int j = 0; j < 8; j++)
        b3[j] = ((xv - gk[j]) * b2[j] + (gk[j + 4] - xv) * b2[j + 1]) * (1.0f / 1.2f);

    unsigned short hs[8];
#pragma unroll
    for (int g = 0; g < GS; g++) {
        __half hv = __float2half(b3[g]);
        hs[g] = *reinterpret_cast<unsigned short*>(&hv);
    }
    uint4 v;
    v.x = (uint32_t)hs[0] | ((uint32_t)hs[1] << 16);
    v.y = (uint32_t)hs[2] | ((uint32_t)hs[3] << 16);
    v.z = (uint32_t)hs[4] | ((uint32_t)hs[5] << 16);
    v.w = (uint32_t)hs[6] | ((uint32_t)hs[7] << 16);
    ((uint4*)g_yh)[idx] = v;
}

// ---------------- kernel 3: fp16 mma.sync conv, A resident across taps --------
// CTA: M=64 pixels (batch b, 2 rows x 32 cols), N=64 outs, 128 thr / 4 warps.
// Warp (wm, wn): m-tile 32 (one output row) x n-tile 32.
// Per 64-ch chunk: A block (4 rows x 34 cols, fp16, 17408 B) staged once,
// 9 taps run from it via shifted addressing; B (8192 B/tap) double-buffered.
static constexpr int A_BYTES = 17408;
static constexpr int B_BYTES = 8192;
static constexpr int SMEM_TOTAL = A_BYTES + 2 * B_BYTES + 256;

__global__ __launch_bounds__(128, 3) void conv_kernel(float* __restrict__ out) {
    extern __shared__ char smem[];
    uint32_t sraw = smem_u32(smem);
    uint32_t sb = (sraw + 255u) & ~255u;
    uint32_t Ab = sb;
    uint32_t Bb0 = sb + A_BYTES;

    int tid = threadIdx.x;
    int blk = blockIdx.x;
    int bb = blk >> 4;
    int h0 = (blk & 15) * 2;

    int lane = tid & 31;
    int wrp = tid >> 5;
    int wm = wrp & 1, wn = wrp >> 1;
    int n0w = wn * 32;

    // ldmatrix fragment geometry (16816)
    int a_row = (lane & 7) + ((lane & 8) ? 8 : 0);            // within 16-block
    int a_seg = (lane & 16) ? 1 : 0;
    int b_rowbase = n0w + (lane & 7) + ((lane & 16) ? 8 : 0); // + nb*16
    int b_seg = (lane & 8) ? 1 : 0;

    float acc[2][2][2][4];        // [mt][nb][fi][i]
#pragma unroll
    for (int a = 0; a < 2; a++)
#pragma unroll
        for (int b = 0; b < 2; b++)
#pragma unroll
            for (int f = 0; f < 2; f++)
#pragma unroll
                for (int i = 0; i < 4; i++) acc[a][b][f][i] = 0.0f;

    const uint4* yh4 = (const uint4*)g_yh;
    const uint4* wh4 = (const uint4*)g_wh;

    // ---- A block stage: 136 pixels x 64 ch fp16 of chunk `ch` ----------------
    // NOTE: one pixel row of g_yh = 512 fp16 = 64 uint4 groups (stride 64!)
    auto issueA = [&](int ch) {
#pragma unroll
        for (int k = 0; k < 9; k++) {
            int q = tid + k * 128;             // 0..1151, need <1088
            if (q < 1088) {
                int pix = q >> 3, c4 = q & 7;
                int r = pix / 34, wp = pix - r * 34;
                uint32_t dst = Ab + pix * 128 + ((c4 ^ (pix & 7)) << 4);
                cp16(dst, yh4 + (((bb * HP + h0 + r) * WP + wp) * 64 + ch * 8 + c4));
            }
        }
    };
    // ---- B tile stage: tap, chunk -> buffer (row stride 64 uint4) ------------
    auto issueB = [&](int tap, int ch, int buf) {
        uint32_t base = Bb0 + buf * B_BYTES;
#pragma unroll
        for (int k = 0; k < 4; k++) {
            int q = tid + k * 128;             // 0..511
            int o = q >> 3, c4 = q & 7;
            uint32_t dst = base + o * 128 + ((c4 ^ (o & 7)) << 4);
            cp16(dst, wh4 + ((tap * COUT + o) * 64 + ch * 8 + c4));
        }
    };

    // ---- compute one tap from resident A + B buffer -------------------------
    auto compute = [&](int tap, int buf) {
        int tk = tap / 3, tl = tap - 3 * tk;
        int pbase = (wm + tk) * 34 + tl;
        uint32_t bbase = Bb0 + buf * B_BYTES;
#pragma unroll
        for (int kc = 0; kc < 4; kc++) {
            uint32_t af[2][4];
#pragma unroll
            for (int mt = 0; mt < 2; mt++) {
                int p = pbase + mt * 16 + a_row;
                uint32_t addr = Ab + p * 128 +
                                (((kc * 2 + a_seg) ^ (p & 7)) << 4);
                ldm4(addr, af[mt][0], af[mt][1], af[mt][2], af[mt][3]);
            }
            uint32_t bf[2][4];
#pragma unroll
            for (int nb = 0; nb < 2; nb++) {
                int nrow = b_rowbase + nb * 16;
                uint32_t addr = bbase + nrow * 128 +
                                (((kc * 2 + b_seg) ^ (nrow & 7)) << 4);
                ldm4(addr, bf[nb][0], bf[nb][1], bf[nb][2], bf[nb][3]);
            }
#pragma unroll
            for (int mt = 0; mt < 2; mt++)
#pragma unroll
                for (int nb = 0; nb < 2; nb++) {
                    mma16816(acc[mt][nb][0], af[mt], bf[nb][0], bf[nb][1]);
                    mma16816(acc[mt][nb][1], af[mt], bf[nb][2], bf[nb][3]);
                }
        }
    };

    // ---- pipeline -----------------------------------------------------------
    issueA(0);
    issueB(0, 0, 0);
    asm volatile("cp.async.commit_group;" ::: "memory");
    asm volatile("cp.async.wait_group 0;" ::: "memory");
    __syncthreads();

    int cur = 0;
    for (int ch = 0; ch < 8; ch++) {
        for (int tap = 0; tap < 9; tap++) {
            bool hn = (tap < 8);
            if (hn) {
                issueB(tap + 1, ch, cur ^ 1);
                asm volatile("cp.async.commit_group;" ::: "memory");
            }
            compute(tap, cur);
            if (hn) asm volatile("cp.async.wait_group 0;" ::: "memory");
            __syncthreads();
            if (hn) cur ^= 1;
        }
        if (ch < 7) {
            issueA(ch + 1);
            issueB(0, ch + 1, cur ^ 1);
            asm volatile("cp.async.commit_group;" ::: "memory");
            asm volatile("cp.async.wait_group 0;" ::: "memory");
            __syncthreads();
            cur ^= 1;
        }
    }

    // ---- epilogue: write out[b][o][h0+wm][wcol] -----------------------------
    int g = lane >> 2;
    int hrow = h0 + wm;
    float* obase = out + ((size_t)bb * COUT) * (H * W) + hrow * W;
#pragma unroll
    for (int mt = 0; mt < 2; mt++)
#pragma unroll
        for (int nb = 0; nb < 2; nb++)
#pragma unroll
            for (int fi = 0; fi < 2; fi++)
#pragma unroll
                for (int i = 0; i < 4; i++) {
                    int wcol = mt * 16 + g + ((i < 2) ? 0 : 8);
                    int o = n0w + nb * 16 + fi * 8 + (lane & 3) * 2 + (i & 1);
                    obase[o * (H * W) + wcol] = acc[mt][nb][fi][i];
                }
}

// ---------------- launch ------------------------------------------------------
extern "C" void kernel_launch(void* const* d_in, const int* in_sizes, int n_in,
                              void* d_out, int out_size) {
    const float* x  = (const float*)d_in[0];   // [16,64,32,32]
    const float* sw = (const float*)d_in[1];   // [64,64,8,3,3]
    const float* sc = (const float*)d_in[2];   // [64,64]
    float* out = (float*)d_out;                // [16,64,32,32]

    cudaFuncSetAttribute(conv_kernel,
                         cudaFuncAttributeMaxDynamicSharedMemorySize,
                         SMEM_TOTAL);

    {
        int n = 9 * COUT * CK;
        wprep_kernel<<<(n + 255) / 256, 256>>>(sw, sc);
    }
    {
        int n = BB * HP * WP * CIN;
        basis_kernel<<<(n + 255) / 256, 256>>>(x);
    }
    conv_kernel<<<BB * (H / 2), 128, SMEM_TOTAL>>>(out);
}